// round 12
// baseline (speedup 1.0000x reference)
#include <cuda_runtime.h>

// ---------------------------------------------------------------------------
// WeightedClassLoss: mean( W[label] * (pred - targ)^2 )
// Exact order statistics of targets at ranks floor(k*(N-1)/5), k=1..4 via
// radix selection on the monotone float->u32 key:
//   K1: 12-bit histogram (full read)        + fused selection (last block)
//   K2: 10-bit hist in 4 selected buckets   + compaction (~8MB) + fused select
//   K3: 10-bit hist over compacted buffer   + fused select -> thresholds
//   K4: weighted-MSE reduction              + fused finalize
// R12: k_hist2 rebuilt — select-chain single atomic per matching element
// (was 5 issued predicated ATOMS per element) and warp-aggregated compaction
// counter (was per-lane single-address shared atomic).
// ---------------------------------------------------------------------------

#define HBLOCKS 304
#define HTHREADS 512
#define CB 8192                              // per-block compaction staging
#define GCAP 12582912                        // global compaction buffer (48MB)

__device__ unsigned g_hist1[4096];           // zero-init; cleaned by K1 last block
__device__ unsigned g_hist2[4][1024];        // cleaned by K2 last block
__device__ unsigned g_hist3[4][1024];        // cleaned by K3 last block
__device__ unsigned g_cbuf[GCAP];
__device__ unsigned g_ccount;                // cleaned by K3 last block
__device__ unsigned g_tick1, g_tick2, g_tick3, g_tick4;   // cleaned by last blocks
__device__ unsigned g_p12[4], g_r12[4];
__device__ unsigned g_p22[4], g_r22[4];
__device__ float    g_thr[4];
__device__ double   g_sum;                   // cleaned by K4 last block

__device__ __forceinline__ unsigned fkey(float f) {
    unsigned u = __float_as_uint(f);
    return (u & 0x80000000u) ? ~u : (u | 0x80000000u);
}

// inclusive block scan over 512 threads (16 warps)
__device__ __forceinline__ unsigned scan512(unsigned x, unsigned* wsum) {
    int lane = threadIdx.x & 31, wid = threadIdx.x >> 5;
    unsigned v = x;
#pragma unroll
    for (int off = 1; off < 32; off <<= 1) {
        unsigned u = __shfl_up_sync(0xffffffffu, v, off);
        if (lane >= off) v += u;
    }
    if (lane == 31) wsum[wid] = v;
    __syncthreads();
    if (wid == 0 && lane < 16) {
        unsigned w = wsum[lane];
#pragma unroll
        for (int off = 1; off < 16; off <<= 1) {
            unsigned u = __shfl_up_sync(0x0000ffffu, w, off);
            if (lane >= off) w += u;
        }
        wsum[lane] = w;
    }
    __syncthreads();
    return v + (wid ? wsum[wid - 1] : 0u);
}

// ---------------------------------------------------------------------------
// K1: 12-bit histogram (4-way MLP) + fused level-1 selection
__global__ void __launch_bounds__(HTHREADS) k_hist1(const float* __restrict__ t,
                                                    int n, int n4, uint4 ranks) {
    __shared__ unsigned sh[4096];
    __shared__ unsigned wsum[16];
    __shared__ int isLast;
    for (int i = threadIdx.x; i < 4096; i += HTHREADS) sh[i] = 0u;
    __syncthreads();
    const float4* tv = reinterpret_cast<const float4*>(t);
    const int stride = gridDim.x * HTHREADS;
    int i = blockIdx.x * HTHREADS + threadIdx.x;
#define H1V(v) { atomicAdd(&sh[fkey(v.x) >> 20], 1u); atomicAdd(&sh[fkey(v.y) >> 20], 1u); \
                 atomicAdd(&sh[fkey(v.z) >> 20], 1u); atomicAdd(&sh[fkey(v.w) >> 20], 1u); }
    for (; i + 3 * stride < n4; i += 4 * stride) {
        float4 a = tv[i];
        float4 b = tv[i + stride];
        float4 c = tv[i + 2 * stride];
        float4 d = tv[i + 3 * stride];
        H1V(a) H1V(b) H1V(c) H1V(d)
    }
    for (; i < n4; i += stride) { float4 a = tv[i]; H1V(a) }
#undef H1V
    int tail = n - (n4 << 2);
    if (blockIdx.x == 0 && threadIdx.x < tail)
        atomicAdd(&sh[fkey(t[(n4 << 2) + threadIdx.x]) >> 20], 1u);
    __syncthreads();
    for (int j = threadIdx.x; j < 4096; j += HTHREADS) {
        unsigned c = sh[j];
        if (c) atomicAdd(&g_hist1[j], c);
    }
    __threadfence();
    if (threadIdx.x == 0)
        isLast = (atomicAdd(&g_tick1, 1u) == gridDim.x - 1u);
    __syncthreads();
    if (!isLast) return;
    __threadfence();
    // ---- fused selection (512 threads, 8 bins/thread) ----
    int tid = threadIdx.x;
    unsigned l[8];
    unsigned sum = 0;
#pragma unroll
    for (int j = 0; j < 8; j++) {
        l[j] = __ldcg(&g_hist1[tid * 8 + j]);
        g_hist1[tid * 8 + j] = 0u;                    // self-clean
        sum += l[j];
    }
    unsigned incl = scan512(sum, wsum);
    unsigned excl = incl - sum;
    unsigned rr[4] = {ranks.x, ranks.y, ranks.z, ranks.w};
#pragma unroll
    for (int s = 0; s < 4; s++) {
        unsigned r = rr[s];
        if (r >= excl && r < incl) {
            unsigned c = excl;
#pragma unroll
            for (int j = 0; j < 8; j++) {
                if (r < c + l[j]) { g_p12[s] = (unsigned)(tid * 8 + j); g_r12[s] = r - c; break; }
                c += l[j];
            }
        }
    }
    if (tid == 0) g_tick1 = 0u;                       // self-clean
}

// ---------------------------------------------------------------------------
// K2: 10-bit hist within selected buckets + compaction + fused selection.
// One shared atomic per MATCHING element (select chain), warp-aggregated
// compaction counter.
__device__ __forceinline__ void h2c_update(unsigned k, unsigned (*sh)[1024],
                                           unsigned p0, unsigned p1, unsigned p2, unsigned p3,
                                           unsigned* cbuf, unsigned* s_ccnt, int lane) {
    unsigned p = k >> 20;
    bool m = (p == p0) | (p == p1) | (p == p2) | (p == p3);
    unsigned mask = __ballot_sync(0xffffffffu, m);
    if (m) {
        int seg = (p == p1) ? 1 : (p == p2) ? 2 : (p == p3) ? 3 : 0;
        atomicAdd(&sh[seg][(k >> 10) & 1023u], 1u);
        unsigned lt = mask & ((1u << lane) - 1u);
        unsigned base = 0u;
        int leader = __ffs(mask) - 1;
        if (lane == leader) base = atomicAdd(s_ccnt, (unsigned)__popc(mask));
        base = __shfl_sync(mask, base, leader);
        unsigned pos = base + (unsigned)__popc(lt);
        if (pos < CB) cbuf[pos] = k;
    }
}

__global__ void __launch_bounds__(HTHREADS) k_hist2(const float* __restrict__ t, int n, int n4) {
    __shared__ unsigned sh[4][1024];
    __shared__ unsigned cbuf[CB];
    __shared__ unsigned s_ccnt, s_base;
    __shared__ unsigned wsum[16];
    __shared__ int isLast;
    unsigned* shp = &sh[0][0];
    for (int i = threadIdx.x; i < 4096; i += HTHREADS) shp[i] = 0u;
    if (threadIdx.x == 0) s_ccnt = 0u;
    __syncthreads();
    unsigned p0 = g_p12[0], p1 = g_p12[1], p2 = g_p12[2], p3 = g_p12[3];
    const int lane = threadIdx.x & 31;
    const float4* tv = reinterpret_cast<const float4*>(t);
    const int stride = gridDim.x * HTHREADS;
    int i = blockIdx.x * HTHREADS + threadIdx.x;
#define H2V(v) { h2c_update(fkey(v.x), sh, p0, p1, p2, p3, cbuf, &s_ccnt, lane); \
                 h2c_update(fkey(v.y), sh, p0, p1, p2, p3, cbuf, &s_ccnt, lane); \
                 h2c_update(fkey(v.z), sh, p0, p1, p2, p3, cbuf, &s_ccnt, lane); \
                 h2c_update(fkey(v.w), sh, p0, p1, p2, p3, cbuf, &s_ccnt, lane); }
    for (; i + 3 * stride < n4; i += 4 * stride) {
        float4 a = tv[i];
        float4 b = tv[i + stride];
        float4 c = tv[i + 2 * stride];
        float4 d = tv[i + 3 * stride];
        H2V(a) H2V(b) H2V(c) H2V(d)
    }
    for (; i < n4; i += stride) { float4 a = tv[i]; H2V(a) }
#undef H2V
    int tail = n - (n4 << 2);
    if (blockIdx.x == 0 && threadIdx.x < tail)
        h2c_update(fkey(t[(n4 << 2) + threadIdx.x]), sh, p0, p1, p2, p3, cbuf, &s_ccnt, lane);
    __syncthreads();
    // single compaction flush (expected ~6.5K << CB)
    {
        unsigned cnt = s_ccnt; if (cnt > CB) cnt = CB;
        if (threadIdx.x == 0 && cnt) s_base = atomicAdd(&g_ccount, cnt);
        __syncthreads();
        for (unsigned q = threadIdx.x; q < cnt; q += HTHREADS) {
            unsigned gp = s_base + q;
            if (gp < GCAP) g_cbuf[gp] = cbuf[q];
        }
    }
    for (int j = threadIdx.x; j < 4096; j += HTHREADS) {
        unsigned c = shp[j];
        if (c) atomicAdd((&g_hist2[0][0]) + j, c);
    }
    __threadfence();
    if (threadIdx.x == 0)
        isLast = (atomicAdd(&g_tick2, 1u) == gridDim.x - 1u);
    __syncthreads();
    if (!isLast) return;
    __threadfence();
    // ---- fused selection (512 threads, 2 bins/thread/segment) ----
    int tid = threadIdx.x;
    for (int s = 0; s < 4; s++) {
        unsigned c0 = __ldcg(&g_hist2[s][tid * 2]);
        unsigned c1 = __ldcg(&g_hist2[s][tid * 2 + 1]);
        g_hist2[s][tid * 2] = 0u; g_hist2[s][tid * 2 + 1] = 0u;   // self-clean
        unsigned sum = c0 + c1;
        unsigned incl = scan512(sum, wsum);
        unsigned excl = incl - sum;
        unsigned r = g_r12[s];
        if (r >= excl && r < incl) {
            unsigned bin = (r < excl + c0) ? (tid * 2) : (tid * 2 + 1);
            g_p22[s] = (g_p12[s] << 10) | bin;
            g_r22[s] = r - ((r < excl + c0) ? excl : (excl + c0));
        }
        __syncthreads();
    }
    if (tid == 0) g_tick2 = 0u;
}

// ---------------------------------------------------------------------------
// K3: 10-bit hist over compacted buffer (~8MB) + fused selection -> thresholds.
// Every compacted key matches one of the 4 prefixes: single atomic, no pred chain.
__device__ __forceinline__ void h3_update(unsigned k, unsigned (*sh)[1024],
                                          unsigned p1, unsigned p2, unsigned p3) {
    unsigned p = k >> 10;
    int seg = (p == p1) ? 1 : (p == p2) ? 2 : (p == p3) ? 3 : 0;
    atomicAdd(&sh[seg][k & 1023u], 1u);
}

__global__ void __launch_bounds__(HTHREADS) k_hist3() {
    __shared__ unsigned sh[4][1024];
    __shared__ unsigned wsum[16];
    __shared__ int isLast;
    unsigned* shp = &sh[0][0];
    for (int i = threadIdx.x; i < 4096; i += HTHREADS) shp[i] = 0u;
    __syncthreads();
    unsigned p1 = g_p22[1], p2 = g_p22[2], p3 = g_p22[3];
    unsigned cnt = g_ccount; if (cnt > GCAP) cnt = GCAP;
    const unsigned stride = gridDim.x * HTHREADS;
    unsigned i = blockIdx.x * HTHREADS + threadIdx.x;
    for (; i + 3 * stride < cnt; i += 4 * stride) {
        unsigned a = g_cbuf[i];
        unsigned b = g_cbuf[i + stride];
        unsigned c = g_cbuf[i + 2 * stride];
        unsigned d = g_cbuf[i + 3 * stride];
        h3_update(a, sh, p1, p2, p3);
        h3_update(b, sh, p1, p2, p3);
        h3_update(c, sh, p1, p2, p3);
        h3_update(d, sh, p1, p2, p3);
    }
    for (; i < cnt; i += stride) h3_update(g_cbuf[i], sh, p1, p2, p3);
    __syncthreads();
    for (int j = threadIdx.x; j < 4096; j += HTHREADS) {
        unsigned c = shp[j];
        if (c) atomicAdd((&g_hist3[0][0]) + j, c);
    }
    __threadfence();
    if (threadIdx.x == 0)
        isLast = (atomicAdd(&g_tick3, 1u) == gridDim.x - 1u);
    __syncthreads();
    if (!isLast) return;
    __threadfence();
    int tid = threadIdx.x;
    for (int s = 0; s < 4; s++) {
        unsigned c0 = __ldcg(&g_hist3[s][tid * 2]);
        unsigned c1 = __ldcg(&g_hist3[s][tid * 2 + 1]);
        g_hist3[s][tid * 2] = 0u; g_hist3[s][tid * 2 + 1] = 0u;   // self-clean
        unsigned sum = c0 + c1;
        unsigned incl = scan512(sum, wsum);
        unsigned excl = incl - sum;
        unsigned r = g_r22[s];
        if (r >= excl && r < incl) {
            unsigned bin = (r < excl + c0) ? (tid * 2) : (tid * 2 + 1);
            unsigned kk = (g_p22[s] << 10) | bin;                 // exact 32-bit key
            unsigned u = (kk & 0x80000000u) ? (kk ^ 0x80000000u) : ~kk;
            g_thr[s] = __uint_as_float(u);
        }
        __syncthreads();
    }
    if (tid == 0) { g_ccount = 0u; g_tick3 = 0u; }                // self-clean
}

// ---------------------------------------------------------------------------
// K4: weighted-MSE reduction + fused finalize
// weight = |1 - c/3|, c = #{i: t > thr_i}:  {1, 2/3, 1/3, ~0, 1/3}
__device__ __forceinline__ float wterm(float p, float t,
                                       float t0, float t1, float t2, float t3) {
    int ci = (t > t0) + (t > t1) + (t > t2) + (t > t3);
    float w = fabsf(1.0f - (float)ci * 0.33333334f);
    float d = p - t;
    return w * d * d;
}

__global__ void __launch_bounds__(HTHREADS) k_loss(const float* __restrict__ pr,
                                                   const float* __restrict__ tg,
                                                   int n, int n4,
                                                   float* __restrict__ out, double inv_n) {
    float t0 = g_thr[0], t1 = g_thr[1], t2 = g_thr[2], t3 = g_thr[3];
    const float4* pv = reinterpret_cast<const float4*>(pr);
    const float4* tv = reinterpret_cast<const float4*>(tg);
    float acc0 = 0.0f, acc1 = 0.0f;
    const int stride = gridDim.x * HTHREADS;
    int i = blockIdx.x * HTHREADS + threadIdx.x;
#define LV(a, b, acc) { acc += wterm(a.x, b.x, t0, t1, t2, t3); acc += wterm(a.y, b.y, t0, t1, t2, t3); \
                        acc += wterm(a.z, b.z, t0, t1, t2, t3); acc += wterm(a.w, b.w, t0, t1, t2, t3); }
    for (; i + 3 * stride < n4; i += 4 * stride) {
        float4 pa = pv[i];
        float4 pb = pv[i + stride];
        float4 pc = pv[i + 2 * stride];
        float4 pd = pv[i + 3 * stride];
        float4 ta = tv[i];
        float4 tb = tv[i + stride];
        float4 tc = tv[i + 2 * stride];
        float4 td = tv[i + 3 * stride];
        LV(pa, ta, acc0) LV(pb, tb, acc1) LV(pc, tc, acc0) LV(pd, td, acc1)
    }
    for (; i < n4; i += stride) {
        float4 pa = pv[i];
        float4 ta = tv[i];
        LV(pa, ta, acc0)
    }
#undef LV
    int tail = n - (n4 << 2);
    if (blockIdx.x == 0 && threadIdx.x < tail) {
        int j = (n4 << 2) + threadIdx.x;
        acc0 += wterm(pr[j], tg[j], t0, t1, t2, t3);
    }
    float acc = acc0 + acc1;
    for (int off = 16; off > 0; off >>= 1)
        acc += __shfl_down_sync(0xffffffffu, acc, off);
    __shared__ float ws[HTHREADS / 32];
    __shared__ int isLast;
    if ((threadIdx.x & 31) == 0) ws[threadIdx.x >> 5] = acc;
    __syncthreads();
    if (threadIdx.x == 0) {
        float s = 0.0f;
        for (int k = 0; k < HTHREADS / 32; k++) s += ws[k];
        atomicAdd(&g_sum, (double)s);
        __threadfence();
        isLast = (atomicAdd(&g_tick4, 1u) == gridDim.x - 1u);
    }
    __syncthreads();
    if (isLast && threadIdx.x == 0) {
        __threadfence();
        double total = __ldcg(&g_sum);
        out[0] = (float)(total * inv_n);
        g_sum = 0.0;                      // self-clean
        g_tick4 = 0u;
    }
}

// ---------------------------------------------------------------------------
extern "C" void kernel_launch(void* const* d_in, const int* in_sizes, int n_in,
                              void* d_out, int out_size) {
    const float* pred = (const float*)d_in[0];
    const float* targ = (const float*)d_in[1];
    int n = in_sizes[0];
    int n4 = n >> 2;
    long long nm1 = (long long)n - 1;
    uint4 ranks;
    ranks.x = (unsigned)((nm1 * 1) / 5);
    ranks.y = (unsigned)((nm1 * 2) / 5);
    ranks.z = (unsigned)((nm1 * 3) / 5);
    ranks.w = (unsigned)((nm1 * 4) / 5);

    int hb = HBLOCKS;
    int maxb = (n4 + HTHREADS - 1) / HTHREADS;
    if (maxb < 1) maxb = 1;
    if (hb > maxb) hb = maxb;

    k_hist1<<<hb, HTHREADS>>>(targ, n, n4, ranks);
    k_hist2<<<hb, HTHREADS>>>(targ, n, n4);
    k_hist3<<<hb, HTHREADS>>>();
    k_loss<<<hb, HTHREADS>>>(pred, targ, n, n4, (float*)d_out, 1.0 / (double)n);
}

// round 14
// speedup vs baseline: 1.2912x; 1.2912x over previous
#include <cuda_runtime.h>

// ---------------------------------------------------------------------------
// WeightedClassLoss: mean( W[label] * (pred - targ)^2 )
// Exact order statistics of targets at ranks floor(k*(N-1)/5), k=1..4 via
// radix selection on the monotone float->u32 key:
//   K1 : 12-bit histogram (full 128MB read) + fused selection (last block)
//   K2 : branch-free compaction of elements in the 4 selected buckets (~8MB)
//        (inline-PTX predicated @p atom/st -- no BSSY, no warp collectives)
//   K3a: 10-bit hist (bits 19:10) over compacted buffer + fused select
//   K3b: 10-bit hist (bits  9:0) over compacted buffer + fused select -> thr
//   K4 : weighted-MSE reduction + fused finalize
// weight index = #{i: t > v_i};  W = |1 - idx/3| (fp32 table to <=1ulp).
// R14 == R13 resubmission (infra failure) + fix: WBUF 768->752 so static
// shared (16*752*4 + 64 = 48,256B) fits under the 48KB static limit.
// ---------------------------------------------------------------------------

#define HBLOCKS 304
#define HTHREADS 512
#define NWARP (HTHREADS / 32)
#define WBUF 752                             // per-warp staging (mean ~408 +17sigma)
#define GCAP 12582912                        // global compaction buffer (48MB)

__device__ unsigned g_hist1[4096];           // zero-init; cleaned by K1 last block
__device__ unsigned g_hist2[4][1024];        // cleaned by K3a last block
__device__ unsigned g_hist3[4][1024];        // cleaned by K3b last block
__device__ unsigned g_cbuf[GCAP];
__device__ unsigned g_ccount;                // cleaned by K3b last block
__device__ unsigned g_tick1, g_tick2, g_tick3, g_tick4;   // cleaned by owners
__device__ unsigned g_p12[4], g_r12[4];
__device__ unsigned g_p22[4], g_r22[4];
__device__ float    g_thr[4];
__device__ double   g_sum;                   // cleaned by K4 last block

__device__ __forceinline__ unsigned fkey(float f) {
    unsigned u = __float_as_uint(f);
    return (u & 0x80000000u) ? ~u : (u | 0x80000000u);
}

// inclusive block scan over 512 threads (16 warps)
__device__ __forceinline__ unsigned scan512(unsigned x, unsigned* wsum) {
    int lane = threadIdx.x & 31, wid = threadIdx.x >> 5;
    unsigned v = x;
#pragma unroll
    for (int off = 1; off < 32; off <<= 1) {
        unsigned u = __shfl_up_sync(0xffffffffu, v, off);
        if (lane >= off) v += u;
    }
    if (lane == 31) wsum[wid] = v;
    __syncthreads();
    if (wid == 0 && lane < 16) {
        unsigned w = wsum[lane];
#pragma unroll
        for (int off = 1; off < 16; off <<= 1) {
            unsigned u = __shfl_up_sync(0x0000ffffu, w, off);
            if (lane >= off) w += u;
        }
        wsum[lane] = w;
    }
    __syncthreads();
    return v + (wid ? wsum[wid - 1] : 0u);
}

// ---------------------------------------------------------------------------
// K1: 12-bit histogram (4-way MLP) + fused level-1 selection
__global__ void __launch_bounds__(HTHREADS) k_hist1(const float* __restrict__ t,
                                                    int n, int n4, uint4 ranks) {
    __shared__ unsigned sh[4096];
    __shared__ unsigned wsum[16];
    __shared__ int isLast;
    for (int i = threadIdx.x; i < 4096; i += HTHREADS) sh[i] = 0u;
    __syncthreads();
    const float4* tv = reinterpret_cast<const float4*>(t);
    const int stride = gridDim.x * HTHREADS;
    int i = blockIdx.x * HTHREADS + threadIdx.x;
#define H1V(v) { atomicAdd(&sh[fkey(v.x) >> 20], 1u); atomicAdd(&sh[fkey(v.y) >> 20], 1u); \
                 atomicAdd(&sh[fkey(v.z) >> 20], 1u); atomicAdd(&sh[fkey(v.w) >> 20], 1u); }
    for (; i + 3 * stride < n4; i += 4 * stride) {
        float4 a = tv[i];
        float4 b = tv[i + stride];
        float4 c = tv[i + 2 * stride];
        float4 d = tv[i + 3 * stride];
        H1V(a) H1V(b) H1V(c) H1V(d)
    }
    for (; i < n4; i += stride) { float4 a = tv[i]; H1V(a) }
#undef H1V
    int tail = n - (n4 << 2);
    if (blockIdx.x == 0 && threadIdx.x < tail)
        atomicAdd(&sh[fkey(t[(n4 << 2) + threadIdx.x]) >> 20], 1u);
    __syncthreads();
    for (int j = threadIdx.x; j < 4096; j += HTHREADS) {
        unsigned c = sh[j];
        if (c) atomicAdd(&g_hist1[j], c);
    }
    __threadfence();
    if (threadIdx.x == 0)
        isLast = (atomicAdd(&g_tick1, 1u) == gridDim.x - 1u);
    __syncthreads();
    if (!isLast) return;
    __threadfence();
    // ---- fused selection (512 threads, 8 bins/thread) ----
    int tid = threadIdx.x;
    unsigned l[8];
    unsigned sum = 0;
#pragma unroll
    for (int j = 0; j < 8; j++) {
        l[j] = __ldcg(&g_hist1[tid * 8 + j]);
        g_hist1[tid * 8 + j] = 0u;                    // self-clean
        sum += l[j];
    }
    unsigned incl = scan512(sum, wsum);
    unsigned excl = incl - sum;
    unsigned rr[4] = {ranks.x, ranks.y, ranks.z, ranks.w};
#pragma unroll
    for (int s = 0; s < 4; s++) {
        unsigned r = rr[s];
        if (r >= excl && r < incl) {
            unsigned c = excl;
#pragma unroll
            for (int j = 0; j < 8; j++) {
                if (r < c + l[j]) { g_p12[s] = (unsigned)(tid * 8 + j); g_r12[s] = r - c; break; }
                c += l[j];
            }
        }
    }
    if (tid == 0) g_tick1 = 0u;                       // self-clean
}

// ---------------------------------------------------------------------------
// K2: branch-free compaction of elements whose 12-bit bucket is selected.
// Predicated inline PTX: no BSSY regions, no warp collectives in the loop.
__device__ __forceinline__ void compact_elem(unsigned k, int m,
                                             unsigned cntAddr, unsigned bufAddr) {
    asm volatile(
        "{\n\t"
        ".reg .pred p, q;\n\t"
        ".reg .u32 r, a;\n\t"
        "setp.ne.u32 p, %0, 0;\n\t"
        "mov.u32 r, 0;\n\t"
        "@p atom.shared.add.u32 r, [%1], 1;\n\t"
        "setp.lt.and.u32 q, r, %4, p;\n\t"
        "mad.lo.u32 a, r, 4, %2;\n\t"
        "@q st.shared.u32 [a], %3;\n\t"
        "}"
        :: "r"(m), "r"(cntAddr), "r"(bufAddr), "r"(k), "n"(WBUF)
        : "memory");
}

__global__ void __launch_bounds__(HTHREADS) k_compact(const float* __restrict__ t,
                                                      int n, int n4) {
    __shared__ unsigned wbuf[NWARP][WBUF];
    __shared__ unsigned wcnt[NWARP];
    int wid = threadIdx.x >> 5, lane = threadIdx.x & 31;
    if (lane == 0) wcnt[wid] = 0u;
    __syncwarp();
    const unsigned p0 = g_p12[0], p1 = g_p12[1], p2 = g_p12[2], p3 = g_p12[3];
    const unsigned cntAddr = (unsigned)__cvta_generic_to_shared(&wcnt[wid]);
    const unsigned bufAddr = (unsigned)__cvta_generic_to_shared(&wbuf[wid][0]);
    const float4* tv = reinterpret_cast<const float4*>(t);
    const int stride = gridDim.x * HTHREADS;
    int i = blockIdx.x * HTHREADS + threadIdx.x;
#define CE(f) { unsigned k = fkey(f); unsigned p = k >> 20; \
                int m = (p == p0) | (p == p1) | (p == p2) | (p == p3); \
                compact_elem(k, m, cntAddr, bufAddr); }
#define CV(v) { CE(v.x) CE(v.y) CE(v.z) CE(v.w) }
    for (; i + 3 * stride < n4; i += 4 * stride) {
        float4 a = tv[i];
        float4 b = tv[i + stride];
        float4 c = tv[i + 2 * stride];
        float4 d = tv[i + 3 * stride];
        CV(a) CV(b) CV(c) CV(d)
    }
    for (; i < n4; i += stride) { float4 a = tv[i]; CV(a) }
    int tail = n - (n4 << 2);
    if (blockIdx.x == 0 && threadIdx.x < tail) { CE(t[(n4 << 2) + threadIdx.x]) }
#undef CV
#undef CE
    // per-warp flush (fully converged; shuffles safe here)
    __syncwarp();
    unsigned cnt = wcnt[wid]; if (cnt > WBUF) cnt = WBUF;
    unsigned base = 0u;
    if (lane == 0 && cnt) base = atomicAdd(&g_ccount, cnt);
    base = __shfl_sync(0xffffffffu, base, 0);
    for (unsigned q = lane; q < cnt; q += 32) {
        unsigned gp = base + q;
        if (gp < GCAP) g_cbuf[gp] = wbuf[wid][q];
    }
}

// ---------------------------------------------------------------------------
// K3a: hist of bits 19:10 over compacted buffer, segmented by selected bucket.
// Four SEPARATE predicated updates (duplicate-bucket safe).
__device__ __forceinline__ void h2_update(unsigned k, unsigned (*sh)[1024],
                                          unsigned p0, unsigned p1, unsigned p2, unsigned p3) {
    unsigned p = k >> 20, b = (k >> 10) & 1023u;
    if (p == p0) atomicAdd(&sh[0][b], 1u);
    if (p == p1) atomicAdd(&sh[1][b], 1u);
    if (p == p2) atomicAdd(&sh[2][b], 1u);
    if (p == p3) atomicAdd(&sh[3][b], 1u);
}

__global__ void __launch_bounds__(HTHREADS) k_hist2c() {
    __shared__ unsigned sh[4][1024];
    __shared__ unsigned wsum[16];
    __shared__ int isLast;
    unsigned* shp = &sh[0][0];
    for (int i = threadIdx.x; i < 4096; i += HTHREADS) shp[i] = 0u;
    __syncthreads();
    unsigned p0 = g_p12[0], p1 = g_p12[1], p2 = g_p12[2], p3 = g_p12[3];
    unsigned cnt = g_ccount; if (cnt > GCAP) cnt = GCAP;
    const unsigned stride = gridDim.x * HTHREADS;
    unsigned i = blockIdx.x * HTHREADS + threadIdx.x;
    for (; i + 3 * stride < cnt; i += 4 * stride) {
        unsigned a = g_cbuf[i];
        unsigned b = g_cbuf[i + stride];
        unsigned c = g_cbuf[i + 2 * stride];
        unsigned d = g_cbuf[i + 3 * stride];
        h2_update(a, sh, p0, p1, p2, p3);
        h2_update(b, sh, p0, p1, p2, p3);
        h2_update(c, sh, p0, p1, p2, p3);
        h2_update(d, sh, p0, p1, p2, p3);
    }
    for (; i < cnt; i += stride) h2_update(g_cbuf[i], sh, p0, p1, p2, p3);
    __syncthreads();
    for (int j = threadIdx.x; j < 4096; j += HTHREADS) {
        unsigned c = shp[j];
        if (c) atomicAdd((&g_hist2[0][0]) + j, c);
    }
    __threadfence();
    if (threadIdx.x == 0)
        isLast = (atomicAdd(&g_tick2, 1u) == gridDim.x - 1u);
    __syncthreads();
    if (!isLast) return;
    __threadfence();
    int tid = threadIdx.x;
    for (int s = 0; s < 4; s++) {
        unsigned c0 = __ldcg(&g_hist2[s][tid * 2]);
        unsigned c1 = __ldcg(&g_hist2[s][tid * 2 + 1]);
        g_hist2[s][tid * 2] = 0u; g_hist2[s][tid * 2 + 1] = 0u;   // self-clean
        unsigned sum = c0 + c1;
        unsigned incl = scan512(sum, wsum);
        unsigned excl = incl - sum;
        unsigned r = g_r12[s];
        if (r >= excl && r < incl) {
            unsigned bin = (r < excl + c0) ? (tid * 2) : (tid * 2 + 1);
            g_p22[s] = (g_p12[s] << 10) | bin;
            g_r22[s] = r - ((r < excl + c0) ? excl : (excl + c0));
        }
        __syncthreads();
    }
    if (tid == 0) g_tick2 = 0u;
}

// ---------------------------------------------------------------------------
// K3b: hist of bits 9:0 over compacted buffer, segmented by 22-bit prefix.
__device__ __forceinline__ void h3_update(unsigned k, unsigned (*sh)[1024],
                                          unsigned p0, unsigned p1, unsigned p2, unsigned p3) {
    unsigned p = k >> 10, b = k & 1023u;
    if (p == p0) atomicAdd(&sh[0][b], 1u);
    if (p == p1) atomicAdd(&sh[1][b], 1u);
    if (p == p2) atomicAdd(&sh[2][b], 1u);
    if (p == p3) atomicAdd(&sh[3][b], 1u);
}

__global__ void __launch_bounds__(HTHREADS) k_hist3c() {
    __shared__ unsigned sh[4][1024];
    __shared__ unsigned wsum[16];
    __shared__ int isLast;
    unsigned* shp = &sh[0][0];
    for (int i = threadIdx.x; i < 4096; i += HTHREADS) shp[i] = 0u;
    __syncthreads();
    unsigned p0 = g_p22[0], p1 = g_p22[1], p2 = g_p22[2], p3 = g_p22[3];
    unsigned cnt = g_ccount; if (cnt > GCAP) cnt = GCAP;
    const unsigned stride = gridDim.x * HTHREADS;
    unsigned i = blockIdx.x * HTHREADS + threadIdx.x;
    for (; i + 3 * stride < cnt; i += 4 * stride) {
        unsigned a = g_cbuf[i];
        unsigned b = g_cbuf[i + stride];
        unsigned c = g_cbuf[i + 2 * stride];
        unsigned d = g_cbuf[i + 3 * stride];
        h3_update(a, sh, p0, p1, p2, p3);
        h3_update(b, sh, p0, p1, p2, p3);
        h3_update(c, sh, p0, p1, p2, p3);
        h3_update(d, sh, p0, p1, p2, p3);
    }
    for (; i < cnt; i += stride) h3_update(g_cbuf[i], sh, p0, p1, p2, p3);
    __syncthreads();
    for (int j = threadIdx.x; j < 4096; j += HTHREADS) {
        unsigned c = shp[j];
        if (c) atomicAdd((&g_hist3[0][0]) + j, c);
    }
    __threadfence();
    if (threadIdx.x == 0)
        isLast = (atomicAdd(&g_tick3, 1u) == gridDim.x - 1u);
    __syncthreads();
    if (!isLast) return;
    __threadfence();
    int tid = threadIdx.x;
    for (int s = 0; s < 4; s++) {
        unsigned c0 = __ldcg(&g_hist3[s][tid * 2]);
        unsigned c1 = __ldcg(&g_hist3[s][tid * 2 + 1]);
        g_hist3[s][tid * 2] = 0u; g_hist3[s][tid * 2 + 1] = 0u;   // self-clean
        unsigned sum = c0 + c1;
        unsigned incl = scan512(sum, wsum);
        unsigned excl = incl - sum;
        unsigned r = g_r22[s];
        if (r >= excl && r < incl) {
            unsigned bin = (r < excl + c0) ? (tid * 2) : (tid * 2 + 1);
            unsigned kk = (g_p22[s] << 10) | bin;                 // exact 32-bit key
            unsigned u = (kk & 0x80000000u) ? (kk ^ 0x80000000u) : ~kk;
            g_thr[s] = __uint_as_float(u);
        }
        __syncthreads();
    }
    if (tid == 0) { g_ccount = 0u; g_tick3 = 0u; }                // self-clean
}

// ---------------------------------------------------------------------------
// K4: weighted-MSE reduction + fused finalize
// weight = |1 - c/3|, c = #{i: t > thr_i}:  {1, 2/3, 1/3, ~0, 1/3}
__device__ __forceinline__ float wterm(float p, float t,
                                       float t0, float t1, float t2, float t3) {
    int ci = (t > t0) + (t > t1) + (t > t2) + (t > t3);
    float w = fabsf(1.0f - (float)ci * 0.33333334f);
    float d = p - t;
    return w * d * d;
}

__global__ void __launch_bounds__(HTHREADS) k_loss(const float* __restrict__ pr,
                                                   const float* __restrict__ tg,
                                                   int n, int n4,
                                                   float* __restrict__ out, double inv_n) {
    float t0 = g_thr[0], t1 = g_thr[1], t2 = g_thr[2], t3 = g_thr[3];
    const float4* pv = reinterpret_cast<const float4*>(pr);
    const float4* tv = reinterpret_cast<const float4*>(tg);
    float acc0 = 0.0f, acc1 = 0.0f;
    const int stride = gridDim.x * HTHREADS;
    int i = blockIdx.x * HTHREADS + threadIdx.x;
#define LV(a, b, acc) { acc += wterm(a.x, b.x, t0, t1, t2, t3); acc += wterm(a.y, b.y, t0, t1, t2, t3); \
                        acc += wterm(a.z, b.z, t0, t1, t2, t3); acc += wterm(a.w, b.w, t0, t1, t2, t3); }
    for (; i + 3 * stride < n4; i += 4 * stride) {
        float4 pa = pv[i];
        float4 pb = pv[i + stride];
        float4 pc = pv[i + 2 * stride];
        float4 pd = pv[i + 3 * stride];
        float4 ta = tv[i];
        float4 tb = tv[i + stride];
        float4 tc = tv[i + 2 * stride];
        float4 td = tv[i + 3 * stride];
        LV(pa, ta, acc0) LV(pb, tb, acc1) LV(pc, tc, acc0) LV(pd, td, acc1)
    }
    for (; i < n4; i += stride) {
        float4 pa = pv[i];
        float4 ta = tv[i];
        LV(pa, ta, acc0)
    }
#undef LV
    int tail = n - (n4 << 2);
    if (blockIdx.x == 0 && threadIdx.x < tail) {
        int j = (n4 << 2) + threadIdx.x;
        acc0 += wterm(pr[j], tg[j], t0, t1, t2, t3);
    }
    float acc = acc0 + acc1;
    for (int off = 16; off > 0; off >>= 1)
        acc += __shfl_down_sync(0xffffffffu, acc, off);
    __shared__ float ws[HTHREADS / 32];
    __shared__ int isLast;
    if ((threadIdx.x & 31) == 0) ws[threadIdx.x >> 5] = acc;
    __syncthreads();
    if (threadIdx.x == 0) {
        float s = 0.0f;
        for (int k = 0; k < HTHREADS / 32; k++) s += ws[k];
        atomicAdd(&g_sum, (double)s);
        __threadfence();
        isLast = (atomicAdd(&g_tick4, 1u) == gridDim.x - 1u);
    }
    __syncthreads();
    if (isLast && threadIdx.x == 0) {
        __threadfence();
        double total = __ldcg(&g_sum);
        out[0] = (float)(total * inv_n);
        g_sum = 0.0;                      // self-clean
        g_tick4 = 0u;
    }
}

// ---------------------------------------------------------------------------
extern "C" void kernel_launch(void* const* d_in, const int* in_sizes, int n_in,
                              void* d_out, int out_size) {
    const float* pred = (const float*)d_in[0];
    const float* targ = (const float*)d_in[1];
    int n = in_sizes[0];
    int n4 = n >> 2;
    long long nm1 = (long long)n - 1;
    uint4 ranks;
    ranks.x = (unsigned)((nm1 * 1) / 5);
    ranks.y = (unsigned)((nm1 * 2) / 5);
    ranks.z = (unsigned)((nm1 * 3) / 5);
    ranks.w = (unsigned)((nm1 * 4) / 5);

    int hb = HBLOCKS;
    int maxb = (n4 + HTHREADS - 1) / HTHREADS;
    if (maxb < 1) maxb = 1;
    if (hb > maxb) hb = maxb;

    k_hist1<<<hb, HTHREADS>>>(targ, n, n4, ranks);
    k_compact<<<hb, HTHREADS>>>(targ, n, n4);
    k_hist2c<<<hb, HTHREADS>>>();
    k_hist3c<<<hb, HTHREADS>>>();
    k_loss<<<hb, HTHREADS>>>(pred, targ, n, n4, (float*)d_out, 1.0 / (double)n);
}